// round 5
// baseline (speedup 1.0000x reference)
#include <cuda_runtime.h>
#include <math.h>

// WaveNet (reference's batch/time mixup: output [64,1,64]; only x[:,:,0:84] used).
//
// R5: one warp per batch element, h register-resident at 3 time points/lane
// (lane l owns t = 3l..3l+2). Neighbor taps via __shfl; no barriers, no
// shared-memory h traffic in the 20-layer loop. Weights staged to SMEM once.
//
// BUG FIX vs R3/R4: skip sums are per-time-point. s0/s1 were single scalars
// shared across the lane's 3 points (all 3 outputs got the summed value,
// rel_err ~0.9). Now s0[3]/s1[3], one accumulator per owned t.

#define N_RES 20
#define FULL 0xFFFFFFFFu

__global__ void __launch_bounds__(32, 1)
wavenet_warp_kernel(const float* __restrict__ x,
                    const float* __restrict__ w_in,
                    const float* __restrict__ b_in,
                    const float* __restrict__ wd,
                    const float* __restrict__ bd,
                    const float* __restrict__ wg,
                    const float* __restrict__ bg,
                    const float* __restrict__ w_out,
                    const float* __restrict__ b_out,
                    float* __restrict__ out)
{
    __shared__ float swd[N_RES * 8];
    __shared__ float swg[N_RES * 8];
    __shared__ float sbd[N_RES * 2];
    __shared__ float sbg[N_RES * 2];

    const int b = blockIdx.x;
    const int l = threadIdx.x;          // lane; owns t = 3l, 3l+1, 3l+2

    // ---- stage weights + biases to SMEM (strided, 32 lanes) ----
    for (int k = l; k < N_RES * 8; k += 32) { swd[k] = wd[k]; swg[k] = wg[k]; }
    for (int k = l; k < N_RES * 2; k += 32) { sbd[k] = bd[k]; sbg[k] = bg[k]; }

    // ---- conv_in: 1x1, C=1 -> F=2 ; h in registers ----
    const float wi0 = w_in[0], wi1 = w_in[1];
    const float bi0 = b_in[0], bi1 = b_in[1];
    float h0[3], h1[3];                 // channel 0 / channel 1
#pragma unroll
    for (int j = 0; j < 3; j++) {
        int t = 3 * l + j;
        float xv = (t < 84) ? x[(size_t)b * 32768 + t] : 0.0f;
        h0[j] = fmaf(wi0, xv, bi0);
        h1[j] = fmaf(wi1, xv, bi1);
    }
    float s0[3] = {0.0f, 0.0f, 0.0f};   // per-time-point skip accumulators
    float s1[3] = {0.0f, 0.0f, 0.0f};
    __syncwarp();                       // SMEM weights visible warp-wide

#pragma unroll
    for (int i = 0; i < N_RES; i++) {
        const bool d1 = (i < 10);

        // right taps c[j] = h[t+1]
        float c0[3], c1[3];
        c0[0] = h0[1]; c0[1] = h0[2];
        c1[0] = h1[1]; c1[1] = h1[2];
        c0[2] = __shfl_down_sync(FULL, h0[0], 1);
        c1[2] = __shfl_down_sync(FULL, h1[0], 1);

        // left taps: d=1 -> h[t]; d=2 -> h[t-1] (zero pad at t=-1)
        float a0[3], a1[3];
        if (d1) {
            a0[0] = h0[0]; a0[1] = h0[1]; a0[2] = h0[2];
            a1[0] = h1[0]; a1[1] = h1[1]; a1[2] = h1[2];
        } else {
            float u0 = __shfl_up_sync(FULL, h0[2], 1);
            float u1 = __shfl_up_sync(FULL, h1[2], 1);
            a0[0] = (l == 0) ? 0.0f : u0;
            a1[0] = (l == 0) ? 0.0f : u1;
            a0[1] = h0[0]; a0[2] = h0[1];
            a1[1] = h1[0]; a1[2] = h1[1];
        }

        const float wd0 = swd[i*8+0], wd1 = swd[i*8+1], wd2 = swd[i*8+2], wd3 = swd[i*8+3];
        const float wd4 = swd[i*8+4], wd5 = swd[i*8+5], wd6 = swd[i*8+6], wd7 = swd[i*8+7];
        const float wg0 = swg[i*8+0], wg1 = swg[i*8+1], wg2 = swg[i*8+2], wg3 = swg[i*8+3];
        const float wg4 = swg[i*8+4], wg5 = swg[i*8+5], wg6 = swg[i*8+6], wg7 = swg[i*8+7];
        const float bd0 = sbd[i*2+0], bd1 = sbd[i*2+1];
        const float bg0 = sbg[i*2+0], bg1 = sbg[i*2+1];

#pragma unroll
        for (int j = 0; j < 3; j++) {
            // balanced FMA trees (depth ~3)
            float cd0 = fmaf(wd0, a0[j], fmaf(wd1, c0[j], bd0))
                      + fmaf(wd2, a1[j], wd3 * c1[j]);
            float cd1 = fmaf(wd4, a0[j], fmaf(wd5, c0[j], bd1))
                      + fmaf(wd6, a1[j], wd7 * c1[j]);
            float cg0 = fmaf(wg0, a0[j], fmaf(wg1, c0[j], bg0))
                      + fmaf(wg2, a1[j], wg3 * c1[j]);
            float cg1 = fmaf(wg4, a0[j], fmaf(wg5, c0[j], bg1))
                      + fmaf(wg6, a1[j], wg7 * c1[j]);

            float g0 = __fdividef(cd0, 1.0f + __expf(-cg0));
            float g1 = __fdividef(cd1, 1.0f + __expf(-cg1));

            s0[j] += g0;                 // per-point skip accumulation
            s1[j] += g1;

            // residual: d=1 -> h'[t] = h[t+1] + g ; d=2 -> h'[t] = h[t] + g
            h0[j] = (d1 ? c0[j] : h0[j]) + g0;
            h1[j] = (d1 ? c1[j] : h1[j]) + g1;
        }
    }

    // ---- conv_out over relu(per-point skip sum) ----
    const float wo0 = w_out[0], wo1 = w_out[1], bo = b_out[0];
#pragma unroll
    for (int j = 0; j < 3; j++) {
        int t = 3 * l + j;
        if (t < 64) {
            out[(size_t)b * 64 + t] =
                fmaf(wo0, fmaxf(s0[j], 0.0f),
                fmaf(wo1, fmaxf(s1[j], 0.0f), bo));
        }
    }
}

extern "C" void kernel_launch(void* const* d_in, const int* in_sizes, int n_in,
                              void* d_out, int out_size)
{
    const float* x     = (const float*)d_in[0];
    const float* w_in  = (const float*)d_in[1];
    const float* b_in  = (const float*)d_in[2];
    const float* wd    = (const float*)d_in[3];
    const float* bd    = (const float*)d_in[4];
    const float* wg    = (const float*)d_in[5];
    const float* bg    = (const float*)d_in[6];
    const float* w_out = (const float*)d_in[7];
    const float* b_out = (const float*)d_in[8];
    float* out = (float*)d_out;

    wavenet_warp_kernel<<<64, 32>>>(x, w_in, b_in, wd, bd, wg, bg,
                                    w_out, b_out, out);
}

// round 6
// speedup vs baseline: 1.5556x; 1.5556x over previous
#include <cuda_runtime.h>
#include <math.h>

// WaveNet (reference's batch/time mixup: output [64,1,64]; only x[:,:,0:84] used).
//
// R6: 2 warps per batch, halo-redundant split -> NO inter-warp communication,
// no barriers in the loop, h register-resident at 2 time points/lane.
//   warp 0: holds t in [0,64),  outputs [0,32)   (right-edge garbage stays >=44)
//   warp 1: holds t in [20,84), outputs [32,64)  (edges valid [30,64) at layer 19)
// Neighbor taps via __shfl within the warp. Weights staged to SMEM once.

#define N_RES 20
#define FULL 0xFFFFFFFFu

__global__ void __launch_bounds__(64, 1)
wavenet_halo_kernel(const float* __restrict__ x,
                    const float* __restrict__ w_in,
                    const float* __restrict__ b_in,
                    const float* __restrict__ wd,
                    const float* __restrict__ bd,
                    const float* __restrict__ wg,
                    const float* __restrict__ bg,
                    const float* __restrict__ w_out,
                    const float* __restrict__ b_out,
                    float* __restrict__ out)
{
    __shared__ __align__(16) float swd[N_RES * 8];
    __shared__ __align__(16) float swg[N_RES * 8];
    __shared__ __align__(16) float sbd[N_RES * 2];
    __shared__ __align__(16) float sbg[N_RES * 2];

    const int b   = blockIdx.x;
    const int tid = threadIdx.x;
    const int w   = tid >> 5;         // warp 0 / 1
    const int l   = tid & 31;

    // ---- stage weights + biases to SMEM ----
    for (int k = tid; k < N_RES * 8; k += 64) { swd[k] = wd[k]; swg[k] = wg[k]; }
    if (tid < N_RES * 2) { sbd[tid] = bd[tid]; sbg[tid] = bg[tid]; }

    const int base = w * 20;          // warp0 holds [0,64), warp1 holds [20,84)
    const int t0   = base + 2 * l;    // slot0 absolute time; slot1 = t0+1

    // output ownership predicates (warp0 -> [0,32), warp1 -> [32,64))
    const bool o0 = w ? (t0     >= 32 && t0     < 64) : (t0     < 32);
    const bool o1 = w ? (t0 + 1 >= 32 && t0 + 1 < 64) : (t0 + 1 < 32);
    const bool pad0 = (w == 0 && l == 0);   // absolute t == 0: left d=2 tap is -1 -> zero

    // ---- conv_in: 1x1, C=1 -> F=2 ----
    const float wi0 = w_in[0], wi1 = w_in[1];
    const float bi0 = b_in[0], bi1 = b_in[1];
    const float xv0 = x[(size_t)b * 32768 + t0];
    const float xv1 = x[(size_t)b * 32768 + t0 + 1];
    float h0[2], h1[2];               // [slot], per channel
    h0[0] = fmaf(wi0, xv0, bi0);  h0[1] = fmaf(wi0, xv1, bi0);
    h1[0] = fmaf(wi1, xv0, bi1);  h1[1] = fmaf(wi1, xv1, bi1);

    float s0[2] = {0.0f, 0.0f};       // per-point skip accumulators
    float s1[2] = {0.0f, 0.0f};

    __syncthreads();                  // SMEM weights ready (once)

#pragma unroll
    for (int i = 0; i < N_RES; i++) {
        const bool d1 = (i < 10);

        // right taps c[slot] = h[t+1]
        float c0s0 = h0[1], c1s0 = h1[1];
        float c0s1 = __shfl_down_sync(FULL, h0[0], 1);
        float c1s1 = __shfl_down_sync(FULL, h1[0], 1);

        // left taps: d=1 -> h[t]; d=2 -> h[t-1] (zero only at absolute t=0)
        float a0s0, a1s0, a0s1, a1s1;
        if (d1) {
            a0s0 = h0[0]; a1s0 = h1[0];
            a0s1 = h0[1]; a1s1 = h1[1];
        } else {
            float u0 = __shfl_up_sync(FULL, h0[1], 1);
            float u1 = __shfl_up_sync(FULL, h1[1], 1);
            a0s0 = pad0 ? 0.0f : u0;
            a1s0 = pad0 ? 0.0f : u1;
            a0s1 = h0[0];
            a1s1 = h1[0];
        }

        const float wd0 = swd[i*8+0], wd1 = swd[i*8+1], wd2 = swd[i*8+2], wd3 = swd[i*8+3];
        const float wd4 = swd[i*8+4], wd5 = swd[i*8+5], wd6 = swd[i*8+6], wd7 = swd[i*8+7];
        const float wg0 = swg[i*8+0], wg1 = swg[i*8+1], wg2 = swg[i*8+2], wg3 = swg[i*8+3];
        const float wg4 = swg[i*8+4], wg5 = swg[i*8+5], wg6 = swg[i*8+6], wg7 = swg[i*8+7];
        const float bd0 = sbd[i*2+0], bd1 = sbd[i*2+1];
        const float bg0 = sbg[i*2+0], bg1 = sbg[i*2+1];

        // ---- slot 0 ----
        {
            float cd0 = fmaf(wd0, a0s0, fmaf(wd1, c0s0, bd0))
                      + fmaf(wd2, a1s0, wd3 * c1s0);
            float cd1 = fmaf(wd4, a0s0, fmaf(wd5, c0s0, bd1))
                      + fmaf(wd6, a1s0, wd7 * c1s0);
            float cg0 = fmaf(wg0, a0s0, fmaf(wg1, c0s0, bg0))
                      + fmaf(wg2, a1s0, wg3 * c1s0);
            float cg1 = fmaf(wg4, a0s0, fmaf(wg5, c0s0, bg1))
                      + fmaf(wg6, a1s0, wg7 * c1s0);
            float g0 = __fdividef(cd0, 1.0f + __expf(-cg0));
            float g1 = __fdividef(cd1, 1.0f + __expf(-cg1));
            if (o0) { s0[0] += g0; s1[0] += g1; }
            h0[0] = (d1 ? c0s0 : h0[0]) + g0;
            h1[0] = (d1 ? c1s0 : h1[0]) + g1;
        }
        // ---- slot 1 ----
        {
            float cd0 = fmaf(wd0, a0s1, fmaf(wd1, c0s1, bd0))
                      + fmaf(wd2, a1s1, wd3 * c1s1);
            float cd1 = fmaf(wd4, a0s1, fmaf(wd5, c0s1, bd1))
                      + fmaf(wd6, a1s1, wd7 * c1s1);
            float cg0 = fmaf(wg0, a0s1, fmaf(wg1, c0s1, bg0))
                      + fmaf(wg2, a1s1, wg3 * c1s1);
            float cg1 = fmaf(wg4, a0s1, fmaf(wg5, c0s1, bg1))
                      + fmaf(wg6, a1s1, wg7 * c1s1);
            float g0 = __fdividef(cd0, 1.0f + __expf(-cg0));
            float g1 = __fdividef(cd1, 1.0f + __expf(-cg1));
            if (o1) { s0[1] += g0; s1[1] += g1; }
            h0[1] = (d1 ? c0s1 : h0[1]) + g0;
            h1[1] = (d1 ? c1s1 : h1[1]) + g1;
        }
    }

    // ---- conv_out over relu(per-point skip sum) ----
    const float wo0 = w_out[0], wo1 = w_out[1], bo = b_out[0];
    if (o0) {
        out[(size_t)b * 64 + t0] =
            fmaf(wo0, fmaxf(s0[0], 0.0f), fmaf(wo1, fmaxf(s1[0], 0.0f), bo));
    }
    if (o1) {
        out[(size_t)b * 64 + t0 + 1] =
            fmaf(wo0, fmaxf(s0[1], 0.0f), fmaf(wo1, fmaxf(s1[1], 0.0f), bo));
    }
}

extern "C" void kernel_launch(void* const* d_in, const int* in_sizes, int n_in,
                              void* d_out, int out_size)
{
    const float* x     = (const float*)d_in[0];
    const float* w_in  = (const float*)d_in[1];
    const float* b_in  = (const float*)d_in[2];
    const float* wd    = (const float*)d_in[3];
    const float* bd    = (const float*)d_in[4];
    const float* wg    = (const float*)d_in[5];
    const float* bg    = (const float*)d_in[6];
    const float* w_out = (const float*)d_in[7];
    const float* b_out = (const float*)d_in[8];
    float* out = (float*)d_out;

    wavenet_halo_kernel<<<64, 64>>>(x, w_in, b_in, wd, bd, wg, bg,
                                    w_out, b_out, out);
}